// round 10
// baseline (speedup 1.0000x reference)
#include <cuda_runtime.h>
#include <cuda_fp16.h>
#include <math.h>
#include <stdint.h>

#define NN 50000
#define EE 600000
#define HH 128
#define GG 128
#define LL 3
#define OUTD 16

// ---------------- scratch (device globals; no allocation) ----------------
__device__ __align__(256) float  g_h[(size_t)NN * HH];    // node features fp32
__device__ __align__(256) __half g_tmp[(size_t)NN * HH];  // GEMM output fp16
__device__ __align__(256) float  g_gate[NN];              // gate logits
__device__ __align__(256) float  g_emb[GG * HH];          // graph embeddings
__device__ __align__(256) float  g_m[GG];                 // per-graph max
__device__ __align__(256) float  g_invs[GG];              // per-graph 1/sumexp
__device__ __align__(1024) __half g_wst[4 * 16384];       // transposed fp16 W
// CSR scratch: packed (col, weight-bits) per edge
__device__ __align__(256) int   g_rowPtr[NN + 1];
__device__ __align__(256) int   g_cursor[NN];
__device__ __align__(256) int2  g_csr[EE];

// ---------------- fp16 MMA helper ----------------
__device__ __forceinline__ void mma_f16(float* c, const uint32_t* a, const uint32_t* b) {
    asm volatile(
        "mma.sync.aligned.m16n8k16.row.col.f32.f16.f16.f32 "
        "{%0,%1,%2,%3},{%4,%5,%6,%7},{%8,%9},{%0,%1,%2,%3};"
        : "+f"(c[0]), "+f"(c[1]), "+f"(c[2]), "+f"(c[3])
        : "r"(a[0]), "r"(a[1]), "r"(a[2]), "r"(a[3]), "r"(b[0]), "r"(b[1]));
}

__device__ __forceinline__ uint32_t h2_u32(__half2 h) {
    return *reinterpret_cast<uint32_t*>(&h);
}

// ---------------- W prep: transpose + fp16 (1 thread per half2) ----------
__global__ void prep_w_kernel(const float* __restrict__ W0,
                              const float* __restrict__ Wc,
                              __half* __restrict__ out)
{
    int i = blockIdx.x * blockDim.x + threadIdx.x;  // 0..32767
    if (i >= 32768) return;
    int wsel = i >> 13;
    int j = i & 8191;
    int n = j >> 6;       // 0..127 output row (N dim)
    int k2 = j & 63;      // k-pair 0..63
    const float* W = (wsel == 0) ? W0 : (Wc + (size_t)(wsel - 1) * 16384);
    __half2 p = __floats2half2_rn(W[(k2 * 2 + 0) * 128 + n],
                                  W[(k2 * 2 + 1) * 128 + n]);
    *(__half2*)(out + (size_t)wsel * 16384 + n * 128 + k2 * 2) = p;
}

// ---------------- fp16 tensor GEMM ----------------
// 64-row tile, 256 threads, 3 CTAs/SM. smem: Wt[128][136]h + A[64][136]h.
#define SPADH 136
#define SPADB (SPADH * 2)
#define GEMM_SMEM_H ((128 * SPADH + 64 * SPADH) * 2)

__global__ void __launch_bounds__(256, 3)
gemm_f16_kernel(const float* __restrict__ A,
                const __half* __restrict__ Wt,
                const float* __restrict__ bias,
                float* __restrict__ Cf,
                __half* __restrict__ Ch,
                int nrows, int doRelu, int outHalf)
{
    extern __shared__ __half smh[];
    char* Wsb = (char*)smh;                       // 128 x 272B
    char* Asb = (char*)(smh + 128 * SPADH);       // 64 x 272B

    int tid = threadIdx.x;
    int rowBase = blockIdx.x << 6;

    // stage W: straight copy of prepped [n][k] fp16 image
    const uint4* Wg = (const uint4*)Wt;
#pragma unroll
    for (int i = tid; i < 2048; i += 256) {
        int r = i >> 4, q = i & 15;
        *(uint4*)(Wsb + r * SPADB + q * 16) = Wg[i];
    }
    // stage A: fp32 -> fp16 convert
    const float4* Ag4 = (const float4*)A;
#pragma unroll
    for (int i = tid; i < 2048; i += 256) {
        int r = i >> 5, c4 = i & 31;
        int gr = rowBase + r;
        float4 v = (gr < nrows) ? Ag4[(size_t)gr * 32 + c4]
                                : make_float4(0.f, 0.f, 0.f, 0.f);
        __half2 p0 = __floats2half2_rn(v.x, v.y);
        __half2 p1 = __floats2half2_rn(v.z, v.w);
        *(uint2*)(Asb + r * SPADB + c4 * 8) = make_uint2(h2_u32(p0), h2_u32(p1));
    }
    __syncthreads();

    int wid = tid >> 5, lane = tid & 31;
    int wm = wid & 1;
    int wn = wid >> 1;
    int gq = lane >> 2;
    int tq = lane & 3;

    float acc[2][4][4];
#pragma unroll
    for (int mi = 0; mi < 2; mi++)
#pragma unroll
        for (int ni = 0; ni < 4; ni++)
#pragma unroll
            for (int j = 0; j < 4; j++) acc[mi][ni][j] = 0.f;

#pragma unroll
    for (int s = 0; s < 8; s++) {
        int kb = (s << 5) + tq * 4;
        uint32_t a[2][4];
#pragma unroll
        for (int mi = 0; mi < 2; mi++) {
            const char* base = Asb + ((wm << 5) + (mi << 4) + gq) * SPADB + kb;
            a[mi][0] = *(const uint32_t*)(base);
            a[mi][1] = *(const uint32_t*)(base + 8 * SPADB);
            a[mi][2] = *(const uint32_t*)(base + 16);
            a[mi][3] = *(const uint32_t*)(base + 8 * SPADB + 16);
        }
        uint32_t b[4][2];
#pragma unroll
        for (int ni = 0; ni < 4; ni++) {
            const char* base = Wsb + ((wn << 5) + (ni << 3) + gq) * SPADB + kb;
            b[ni][0] = *(const uint32_t*)(base);
            b[ni][1] = *(const uint32_t*)(base + 16);
        }
#pragma unroll
        for (int mi = 0; mi < 2; mi++)
#pragma unroll
            for (int ni = 0; ni < 4; ni++)
                mma_f16(acc[mi][ni], a[mi], b[ni]);
    }

#pragma unroll
    for (int mi = 0; mi < 2; mi++) {
        int r0 = rowBase + (wm << 5) + (mi << 4) + gq;
#pragma unroll
        for (int ni = 0; ni < 4; ni++) {
            int col = (wn << 5) + (ni << 3) + (tq << 1);
            float b0 = bias[col], b1 = bias[col + 1];
            float v0 = acc[mi][ni][0] + b0, v1 = acc[mi][ni][1] + b1;
            float v2 = acc[mi][ni][2] + b0, v3 = acc[mi][ni][3] + b1;
            if (doRelu) {
                v0 = fmaxf(v0, 0.f); v1 = fmaxf(v1, 0.f);
                v2 = fmaxf(v2, 0.f); v3 = fmaxf(v3, 0.f);
            }
            if (outHalf) {
                if (r0 < nrows)
                    *(uint32_t*)(Ch + (size_t)r0 * 128 + col) = h2_u32(__floats2half2_rn(v0, v1));
                if (r0 + 8 < nrows)
                    *(uint32_t*)(Ch + (size_t)(r0 + 8) * 128 + col) = h2_u32(__floats2half2_rn(v2, v3));
            } else {
                if (r0 < nrows)     *(float2*)(Cf + (size_t)r0 * 128 + col)       = make_float2(v0, v1);
                if (r0 + 8 < nrows) *(float2*)(Cf + (size_t)(r0 + 8) * 128 + col) = make_float2(v2, v3);
            }
        }
    }
}

// ---------------- CSR build (scalar, packed payload) ----------------------
__global__ void deg_kernel(const int* __restrict__ er, int* __restrict__ deg)
{
    int e = blockIdx.x * blockDim.x + threadIdx.x;
    if (e < EE) atomicAdd(&deg[er[e]], 1);
}

__global__ void scan_kernel(int* __restrict__ cursor, int* __restrict__ rowPtr)
{
    const int PER = (NN + 1023) / 1024;
    int tid = threadIdx.x;
    int base = tid * PER;

    int s = 0;
    for (int i = 0; i < PER; i++) {
        int idx = base + i;
        if (idx < NN) s += cursor[idx];
    }
    int lane = tid & 31, wid = tid >> 5;
    int ws = s;
#pragma unroll
    for (int off = 1; off < 32; off <<= 1) {
        int n = __shfl_up_sync(0xFFFFFFFFu, ws, off);
        if (lane >= off) ws += n;
    }
    __shared__ int wsum[32];
    if (lane == 31) wsum[wid] = ws;
    __syncthreads();
    if (wid == 0) {
        int v = wsum[lane];
#pragma unroll
        for (int off = 1; off < 32; off <<= 1) {
            int n = __shfl_up_sync(0xFFFFFFFFu, v, off);
            if (lane >= off) v += n;
        }
        wsum[lane] = v;
    }
    __syncthreads();
    int offset = ws - s + (wid ? wsum[wid - 1] : 0);

    int run = offset;
    for (int i = 0; i < PER; i++) {
        int idx = base + i;
        if (idx < NN) {
            int v = cursor[idx];
            rowPtr[idx] = run;
            cursor[idx] = run;
            run += v;
        }
    }
    if (tid == 1023) rowPtr[NN] = run;
}

__global__ void fill_kernel(const int* __restrict__ er, const int* __restrict__ ec,
                            const float* __restrict__ ew,
                            int* __restrict__ cursor,
                            int2* __restrict__ csr)
{
    int e = blockIdx.x * blockDim.x + threadIdx.x;
    if (e >= EE) return;
    int r = er[e];
    int c = ec[e];
    float w = ew[e];
    int pos = atomicAdd(&cursor[r], 1);
    csr[pos] = make_int2(c, __float_as_int(w));
}

// ------- fused SpMM-gather(fp16) + BN + ReLU + residual (+opt gate) -------
// one 16-lane group per row; lane owns 8 features (uint4 = 16B of fp16).
// Row stride in uint4 units: 128 halves = 16 uint4. (R9 bug: used 8.)
__global__ void spmm_fused_kernel(const __half* __restrict__ hn,
                                  const int* __restrict__ rowPtr,
                                  const int2* __restrict__ csr,
                                  float* __restrict__ h,
                                  const float* __restrict__ gamma,
                                  const float* __restrict__ beta,
                                  const float* __restrict__ mean,
                                  const float* __restrict__ var,
                                  const float* __restrict__ gateW,
                                  const float* __restrict__ gateB,
                                  float* __restrict__ gateOut,
                                  int doGate)
{
    __shared__ float sc[128], sh[128];
    if (threadIdx.x < 128) {
        int j = threadIdx.x;
        float s = gamma[j] * rsqrtf(var[j] + 1e-5f);
        sc[j] = s;
        sh[j] = beta[j] - mean[j] * s;
    }
    __syncthreads();

    int idx = blockIdx.x * blockDim.x + threadIdx.x;
    int row = idx >> 4;
    int lane = idx & 15;         // owns halves [lane*8, lane*8+8)
    if (row >= NN) return;

    int start = rowPtr[row];
    int end = rowPtr[row + 1];

    float s0 = 0.f, s1 = 0.f, s2 = 0.f, s3 = 0.f;
    float s4 = 0.f, s5 = 0.f, s6 = 0.f, s7 = 0.f;
    const uint4* hn4 = (const uint4*)hn;
#pragma unroll 4
    for (int j = start; j < end; j++) {
        int2 e = __ldg(&csr[j]);     // uniform across 16-lane group
        float w = __int_as_float(e.y);
        uint4 u = hn4[(size_t)e.x * 16 + lane];   // FIXED: stride 16 uint4/row
        float2 f0 = __half22float2(*reinterpret_cast<__half2*>(&u.x));
        float2 f1 = __half22float2(*reinterpret_cast<__half2*>(&u.y));
        float2 f2 = __half22float2(*reinterpret_cast<__half2*>(&u.z));
        float2 f3 = __half22float2(*reinterpret_cast<__half2*>(&u.w));
        s0 += w * f0.x; s1 += w * f0.y;
        s2 += w * f1.x; s3 += w * f1.y;
        s4 += w * f2.x; s5 += w * f2.y;
        s6 += w * f3.x; s7 += w * f3.y;
    }

    int fb = lane * 8;   // first feature index owned by this lane
    float4* hrow = (float4*)(h + (size_t)row * 128 + fb);
    float4 hv0 = hrow[0];
    float4 hv1 = hrow[1];
    hv0.x += fmaxf(fmaf(s0, sc[fb + 0], sh[fb + 0]), 0.f);
    hv0.y += fmaxf(fmaf(s1, sc[fb + 1], sh[fb + 1]), 0.f);
    hv0.z += fmaxf(fmaf(s2, sc[fb + 2], sh[fb + 2]), 0.f);
    hv0.w += fmaxf(fmaf(s3, sc[fb + 3], sh[fb + 3]), 0.f);
    hv1.x += fmaxf(fmaf(s4, sc[fb + 4], sh[fb + 4]), 0.f);
    hv1.y += fmaxf(fmaf(s5, sc[fb + 5], sh[fb + 5]), 0.f);
    hv1.z += fmaxf(fmaf(s6, sc[fb + 6], sh[fb + 6]), 0.f);
    hv1.w += fmaxf(fmaf(s7, sc[fb + 7], sh[fb + 7]), 0.f);
    hrow[0] = hv0;
    hrow[1] = hv1;

    if (doGate) {
        const float4* gw4 = (const float4*)(gateW + fb);
        float4 g0 = gw4[0], g1 = gw4[1];
        float d = hv0.x * g0.x + hv0.y * g0.y + hv0.z * g0.z + hv0.w * g0.w
                + hv1.x * g1.x + hv1.y * g1.y + hv1.z * g1.z + hv1.w * g1.w;
        // reduce across the 16-lane group (xor offsets stay in-group)
#pragma unroll
        for (int off = 8; off; off >>= 1) d += __shfl_xor_sync(0xFFFFFFFFu, d, off);
        if (lane == 0) gateOut[row] = d + gateB[0];
    }
}

// ---------------- per-graph softmax stats (max, 1/sumexp) ----------------
__global__ void seg_stats_kernel(const float* __restrict__ g,
                                 const int* __restrict__ batch,
                                 float* __restrict__ mOut,
                                 float* __restrict__ invOut)
{
    int b = blockIdx.x;
    int tid = threadIdx.x;  // 128

    int lo = 0, hi = NN;
    while (lo < hi) { int mid = (lo + hi) >> 1; if (batch[mid] < b) lo = mid + 1; else hi = mid; }
    int start = lo;
    hi = NN;
    while (lo < hi) { int mid = (lo + hi) >> 1; if (batch[mid] < b + 1) lo = mid + 1; else hi = mid; }
    int end = lo;

    __shared__ float red[128];
    float lm = -3.402823466e38f;
    for (int i = start + tid; i < end; i += 128) lm = fmaxf(lm, g[i]);
    red[tid] = lm; __syncthreads();
    for (int s = 64; s; s >>= 1) { if (tid < s) red[tid] = fmaxf(red[tid], red[tid + s]); __syncthreads(); }
    float m = red[0]; __syncthreads();

    float ls = 0.f;
    for (int i = start + tid; i < end; i += 128) ls += expf(g[i] - m);
    red[tid] = ls; __syncthreads();
    for (int s = 64; s; s >>= 1) { if (tid < s) red[tid] += red[tid + s]; __syncthreads(); }
    if (tid == 0) { mOut[b] = m; invOut[b] = 1.f / (red[0] + 1e-10f); }
}

// ---------------- weighted-sum pooling (bandwidth-parallel) ---------------
__global__ void pool_accum_kernel(const float* __restrict__ h,
                                  const float* __restrict__ g,
                                  const int* __restrict__ batch,
                                  const float* __restrict__ mIn,
                                  const float* __restrict__ invIn,
                                  float* __restrict__ emb)
{
    __shared__ float coef[256];
    __shared__ int sbat[256];
    int tid = threadIdx.x;      // 128
    int base = blockIdx.x * 256;
    if (base >= NN) return;

    for (int j = tid; j < 256; j += 128) {
        int i = base + j;
        if (i < NN) {
            int bb = batch[i];
            sbat[j] = bb;
            coef[j] = expf(g[i] - mIn[bb]) * invIn[bb];
        } else {
            sbat[j] = batch[NN - 1];
            coef[j] = 0.f;
        }
    }
    __syncthreads();

    float acc = 0.f;
    int cur = sbat[0];
    int cnt = min(256, NN - base);
#pragma unroll 4
    for (int j = 0; j < 256; j++) {
        if (j >= cnt) break;
        int bb = sbat[j];
        if (bb != cur) {
            atomicAdd(&emb[cur * 128 + tid], acc);
            acc = 0.f;
            cur = bb;
        }
        acc += coef[j] * h[(size_t)(base + j) * 128 + tid];
    }
    atomicAdd(&emb[cur * 128 + tid], acc);
}

// ---------------- head MLP ------------------------------------------------
__global__ void head_kernel(const float* __restrict__ emb,
                            const float* __restrict__ W1,
                            const float* __restrict__ b1,
                            const float* __restrict__ W2,
                            const float* __restrict__ b2,
                            float* __restrict__ out)
{
    int b = blockIdx.x;
    int tid = threadIdx.x;  // 128
    __shared__ float se[128], st[128];
    se[tid] = emb[b * 128 + tid];
    __syncthreads();
    float acc = b1[tid];
#pragma unroll 8
    for (int k = 0; k < 128; k++) acc += se[k] * W1[k * 128 + tid];
    st[tid] = fmaxf(acc, 0.f);
    __syncthreads();
    if (tid < OUTD) {
        float o = b2[tid];
#pragma unroll 8
        for (int k = 0; k < 128; k++) o += st[k] * W2[k * OUTD + tid];
        out[b * OUTD + tid] = o;
    }
}

// ---------------- launcher ----------------------------------------------
extern "C" void kernel_launch(void* const* d_in, const int* in_sizes, int n_in,
                              void* d_out, int out_size)
{
    const float* x        = (const float*)d_in[0];
    const float* edge_w   = (const float*)d_in[1];
    const float* W_in     = (const float*)d_in[2];
    const float* b_in     = (const float*)d_in[3];
    const float* conv_W   = (const float*)d_in[4];
    const float* conv_b   = (const float*)d_in[5];
    const float* bn_gamma = (const float*)d_in[6];
    const float* bn_beta  = (const float*)d_in[7];
    const float* bn_mean  = (const float*)d_in[8];
    const float* bn_var   = (const float*)d_in[9];
    const float* gate_W   = (const float*)d_in[10];
    const float* gate_b   = (const float*)d_in[11];
    const float* head_W1  = (const float*)d_in[12];
    const float* head_b1  = (const float*)d_in[13];
    const float* head_W2  = (const float*)d_in[14];
    const float* head_b2  = (const float*)d_in[15];
    const int*   er       = (const int*)d_in[16];
    const int*   ec       = (const int*)d_in[17];
    const int*   batch    = (const int*)d_in[18];
    float* out = (float*)d_out;

    float *h, *gate, *emb, *mArr, *invArr;
    __half *tmp, *wst;
    int *rowPtr, *cursor;
    int2 *csr;
    cudaGetSymbolAddress((void**)&h,      g_h);
    cudaGetSymbolAddress((void**)&tmp,    g_tmp);
    cudaGetSymbolAddress((void**)&gate,   g_gate);
    cudaGetSymbolAddress((void**)&emb,    g_emb);
    cudaGetSymbolAddress((void**)&mArr,   g_m);
    cudaGetSymbolAddress((void**)&invArr, g_invs);
    cudaGetSymbolAddress((void**)&rowPtr, g_rowPtr);
    cudaGetSymbolAddress((void**)&cursor, g_cursor);
    cudaGetSymbolAddress((void**)&csr,    g_csr);
    cudaGetSymbolAddress((void**)&wst,    g_wst);

    cudaFuncSetAttribute(gemm_f16_kernel,
                         cudaFuncAttributeMaxDynamicSharedMemorySize, GEMM_SMEM_H);

    const int gemmGrid = (NN + 63) / 64;            // 782
    const int edgeGrid = (EE + 255) / 256;          // 2344
    const int spmmGrid = (NN * 16 + 255) / 256;     // 3125
    const int poolGrid = (NN + 255) / 256;          // 196

    // ---- fork: CSR build on side stream, overlapped with prep + GEMMs ----
    cudaStream_t s2;
    cudaEvent_t evFork, evJoin;
    cudaStreamCreateWithFlags(&s2, cudaStreamNonBlocking);
    cudaEventCreateWithFlags(&evFork, cudaEventDisableTiming);
    cudaEventCreateWithFlags(&evJoin, cudaEventDisableTiming);

    cudaEventRecord(evFork, 0);
    cudaStreamWaitEvent(s2, evFork, 0);

    // side stream: CSR build chain
    cudaMemsetAsync(cursor, 0, NN * sizeof(int), s2);
    deg_kernel<<<edgeGrid, 256, 0, s2>>>(er, cursor);
    scan_kernel<<<1, 1024, 0, s2>>>(cursor, rowPtr);
    fill_kernel<<<edgeGrid, 256, 0, s2>>>(er, ec, edge_w, cursor, csr);
    cudaEventRecord(evJoin, s2);

    // main stream: weight prep + input projection + first conv GEMM
    prep_w_kernel<<<128, 256>>>(W_in, conv_W, wst);
    gemm_f16_kernel<<<gemmGrid, 256, GEMM_SMEM_H>>>(x, wst, b_in, h, (__half*)0,
                                                    NN, 1, 0);
    gemm_f16_kernel<<<gemmGrid, 256, GEMM_SMEM_H>>>(
        h, wst + (size_t)1 * 16384, conv_b + 0 * HH, (float*)0, tmp, NN, 0, 1);

    // join: first spmm needs the CSR
    cudaStreamWaitEvent(0, evJoin, 0);

    for (int l = 0; l < LL; l++) {
        if (l > 0) {
            gemm_f16_kernel<<<gemmGrid, 256, GEMM_SMEM_H>>>(
                h, wst + (size_t)(l + 1) * 16384, conv_b + l * HH,
                (float*)0, tmp, NN, 0, 1);
        }
        spmm_fused_kernel<<<spmmGrid, 256>>>(tmp, rowPtr, csr, h,
                                             bn_gamma + l * HH, bn_beta + l * HH,
                                             bn_mean + l * HH, bn_var + l * HH,
                                             gate_W, gate_b, gate,
                                             (l == LL - 1) ? 1 : 0);
    }

    seg_stats_kernel<<<GG, 128>>>(gate, batch, mArr, invArr);
    cudaMemsetAsync(emb, 0, GG * HH * sizeof(float));
    pool_accum_kernel<<<poolGrid, 128>>>(h, gate, batch, mArr, invArr, emb);
    head_kernel<<<GG, 128>>>(emb, head_W1, head_b1, head_W2, head_b2, out);

    cudaEventDestroy(evFork);
    cudaEventDestroy(evJoin);
    cudaStreamDestroy(s2);
}

// round 11
// speedup vs baseline: 1.0609x; 1.0609x over previous
#include <cuda_runtime.h>
#include <cuda_fp16.h>
#include <math.h>
#include <stdint.h>

#define NN 50000
#define EE 600000
#define HH 128
#define GG 128
#define LL 3
#define OUTD 16

// ---------------- scratch (device globals; no allocation) ----------------
__device__ __align__(256) float  g_h[(size_t)NN * HH];    // node features fp32
__device__ __align__(256) __half g_tmp[(size_t)NN * HH];  // GEMM output fp16
__device__ __align__(256) float  g_gate[NN];              // gate logits
__device__ __align__(256) float  g_emb[GG * HH];          // graph embeddings
__device__ __align__(256) float  g_m[GG];                 // per-graph max
__device__ __align__(256) float  g_invs[GG];              // per-graph 1/sumexp
__device__ __align__(1024) __half g_wst[4 * 16384];       // transposed fp16 W
// CSR scratch: packed (col, weight-bits) per edge
__device__ __align__(256) int   g_rowPtr[NN + 1];
__device__ __align__(256) int   g_cursor[NN];
__device__ __align__(256) int2  g_csr[EE];

// ---------------- fp16 MMA helper ----------------
__device__ __forceinline__ void mma_f16(float* c, const uint32_t* a, const uint32_t* b) {
    asm volatile(
        "mma.sync.aligned.m16n8k16.row.col.f32.f16.f16.f32 "
        "{%0,%1,%2,%3},{%4,%5,%6,%7},{%8,%9},{%0,%1,%2,%3};"
        : "+f"(c[0]), "+f"(c[1]), "+f"(c[2]), "+f"(c[3])
        : "r"(a[0]), "r"(a[1]), "r"(a[2]), "r"(a[3]), "r"(b[0]), "r"(b[1]));
}

__device__ __forceinline__ uint32_t h2_u32(__half2 h) {
    return *reinterpret_cast<uint32_t*>(&h);
}

// ---------------- W prep: transpose + fp16 (coalesced reads) -------------
// Thread mapping: n fastest -> reads of W[k][n] are fully coalesced.
// Writes out[n*128+k] are scattered (stores don't stall).
__global__ void prep_w_kernel(const float* __restrict__ W0,
                              const float* __restrict__ Wc,
                              __half* __restrict__ out)
{
    int i = blockIdx.x * blockDim.x + threadIdx.x;  // 0..32767
    if (i >= 32768) return;
    int wsel = i >> 13;
    int j = i & 8191;
    int n = j & 127;      // fastest -> coalesced read of W rows
    int k2 = j >> 7;      // k-pair 0..63
    const float* W = (wsel == 0) ? W0 : (Wc + (size_t)(wsel - 1) * 16384);
    __half2 p = __floats2half2_rn(W[(k2 * 2 + 0) * 128 + n],
                                  W[(k2 * 2 + 1) * 128 + n]);
    *(__half2*)(out + (size_t)wsel * 16384 + n * 128 + k2 * 2) = p;
}

// ---------------- fp16 tensor GEMM ----------------
// 64-row tile, 256 threads, 3 CTAs/SM. smem: Wt[128][136]h + A[64][136]h.
#define SPADH 136
#define SPADB (SPADH * 2)
#define GEMM_SMEM_H ((128 * SPADH + 64 * SPADH) * 2)

__global__ void __launch_bounds__(256, 3)
gemm_f16_kernel(const float* __restrict__ A,
                const __half* __restrict__ Wt,
                const float* __restrict__ bias,
                float* __restrict__ Cf,
                __half* __restrict__ Ch,
                int nrows, int doRelu, int outHalf)
{
    extern __shared__ __half smh[];
    char* Wsb = (char*)smh;                       // 128 x 272B
    char* Asb = (char*)(smh + 128 * SPADH);       // 64 x 272B

    int tid = threadIdx.x;
    int rowBase = blockIdx.x << 6;

    // stage W: straight copy of prepped [n][k] fp16 image
    const uint4* Wg = (const uint4*)Wt;
#pragma unroll
    for (int i = tid; i < 2048; i += 256) {
        int r = i >> 4, q = i & 15;
        *(uint4*)(Wsb + r * SPADB + q * 16) = Wg[i];
    }
    // stage A: fp32 -> fp16 convert
    const float4* Ag4 = (const float4*)A;
#pragma unroll
    for (int i = tid; i < 2048; i += 256) {
        int r = i >> 5, c4 = i & 31;
        int gr = rowBase + r;
        float4 v = (gr < nrows) ? Ag4[(size_t)gr * 32 + c4]
                                : make_float4(0.f, 0.f, 0.f, 0.f);
        __half2 p0 = __floats2half2_rn(v.x, v.y);
        __half2 p1 = __floats2half2_rn(v.z, v.w);
        *(uint2*)(Asb + r * SPADB + c4 * 8) = make_uint2(h2_u32(p0), h2_u32(p1));
    }
    __syncthreads();

    int wid = tid >> 5, lane = tid & 31;
    int wm = wid & 1;
    int wn = wid >> 1;
    int gq = lane >> 2;
    int tq = lane & 3;

    float acc[2][4][4];
#pragma unroll
    for (int mi = 0; mi < 2; mi++)
#pragma unroll
        for (int ni = 0; ni < 4; ni++)
#pragma unroll
            for (int j = 0; j < 4; j++) acc[mi][ni][j] = 0.f;

#pragma unroll
    for (int s = 0; s < 8; s++) {
        int kb = (s << 5) + tq * 4;
        uint32_t a[2][4];
#pragma unroll
        for (int mi = 0; mi < 2; mi++) {
            const char* base = Asb + ((wm << 5) + (mi << 4) + gq) * SPADB + kb;
            a[mi][0] = *(const uint32_t*)(base);
            a[mi][1] = *(const uint32_t*)(base + 8 * SPADB);
            a[mi][2] = *(const uint32_t*)(base + 16);
            a[mi][3] = *(const uint32_t*)(base + 8 * SPADB + 16);
        }
        uint32_t b[4][2];
#pragma unroll
        for (int ni = 0; ni < 4; ni++) {
            const char* base = Wsb + ((wn << 5) + (ni << 3) + gq) * SPADB + kb;
            b[ni][0] = *(const uint32_t*)(base);
            b[ni][1] = *(const uint32_t*)(base + 16);
        }
#pragma unroll
        for (int mi = 0; mi < 2; mi++)
#pragma unroll
            for (int ni = 0; ni < 4; ni++)
                mma_f16(acc[mi][ni], a[mi], b[ni]);
    }

#pragma unroll
    for (int mi = 0; mi < 2; mi++) {
        int r0 = rowBase + (wm << 5) + (mi << 4) + gq;
#pragma unroll
        for (int ni = 0; ni < 4; ni++) {
            int col = (wn << 5) + (ni << 3) + (tq << 1);
            float b0 = bias[col], b1 = bias[col + 1];
            float v0 = acc[mi][ni][0] + b0, v1 = acc[mi][ni][1] + b1;
            float v2 = acc[mi][ni][2] + b0, v3 = acc[mi][ni][3] + b1;
            if (doRelu) {
                v0 = fmaxf(v0, 0.f); v1 = fmaxf(v1, 0.f);
                v2 = fmaxf(v2, 0.f); v3 = fmaxf(v3, 0.f);
            }
            if (outHalf) {
                if (r0 < nrows)
                    *(uint32_t*)(Ch + (size_t)r0 * 128 + col) = h2_u32(__floats2half2_rn(v0, v1));
                if (r0 + 8 < nrows)
                    *(uint32_t*)(Ch + (size_t)(r0 + 8) * 128 + col) = h2_u32(__floats2half2_rn(v2, v3));
            } else {
                if (r0 < nrows)     *(float2*)(Cf + (size_t)r0 * 128 + col)       = make_float2(v0, v1);
                if (r0 + 8 < nrows) *(float2*)(Cf + (size_t)(r0 + 8) * 128 + col) = make_float2(v2, v3);
            }
        }
    }
}

// ---------------- CSR build (scalar, packed payload) ----------------------
__global__ void deg_kernel(const int* __restrict__ er, int* __restrict__ deg)
{
    int e = blockIdx.x * blockDim.x + threadIdx.x;
    if (e < EE) atomicAdd(&deg[er[e]], 1);
}

__global__ void scan_kernel(int* __restrict__ cursor, int* __restrict__ rowPtr)
{
    const int PER = (NN + 1023) / 1024;
    int tid = threadIdx.x;
    int base = tid * PER;

    int s = 0;
    for (int i = 0; i < PER; i++) {
        int idx = base + i;
        if (idx < NN) s += cursor[idx];
    }
    int lane = tid & 31, wid = tid >> 5;
    int ws = s;
#pragma unroll
    for (int off = 1; off < 32; off <<= 1) {
        int n = __shfl_up_sync(0xFFFFFFFFu, ws, off);
        if (lane >= off) ws += n;
    }
    __shared__ int wsum[32];
    if (lane == 31) wsum[wid] = ws;
    __syncthreads();
    if (wid == 0) {
        int v = wsum[lane];
#pragma unroll
        for (int off = 1; off < 32; off <<= 1) {
            int n = __shfl_up_sync(0xFFFFFFFFu, v, off);
            if (lane >= off) v += n;
        }
        wsum[lane] = v;
    }
    __syncthreads();
    int offset = ws - s + (wid ? wsum[wid - 1] : 0);

    int run = offset;
    for (int i = 0; i < PER; i++) {
        int idx = base + i;
        if (idx < NN) {
            int v = cursor[idx];
            rowPtr[idx] = run;
            cursor[idx] = run;
            run += v;
        }
    }
    if (tid == 1023) rowPtr[NN] = run;
}

__global__ void fill_kernel(const int* __restrict__ er, const int* __restrict__ ec,
                            const float* __restrict__ ew,
                            int* __restrict__ cursor,
                            int2* __restrict__ csr)
{
    int e = blockIdx.x * blockDim.x + threadIdx.x;
    if (e >= EE) return;
    int r = er[e];
    int c = ec[e];
    float w = ew[e];
    int pos = atomicAdd(&cursor[r], 1);
    csr[pos] = make_int2(c, __float_as_int(w));
}

// ------- fused SpMM-gather(fp16) + BN + ReLU + residual (+opt gate) -------
// DUAL-ROW: one warp handles rows 2w and 2w+1 with interleaved loops.
// Every gather keeps the R7 pattern (32 lanes x 8B = one 256B segment per
// instruction). Trip count = max(d0,d1): uniform -> no divergence. OOB
// iterations are predicated off -> no extra memory traffic.
__global__ void spmm_fused_kernel(const __half* __restrict__ hn,
                                  const int* __restrict__ rowPtr,
                                  const int2* __restrict__ csr,
                                  float* __restrict__ h,
                                  const float* __restrict__ gamma,
                                  const float* __restrict__ beta,
                                  const float* __restrict__ mean,
                                  const float* __restrict__ var,
                                  const float* __restrict__ gateW,
                                  const float* __restrict__ gateB,
                                  float* __restrict__ gateOut,
                                  int doGate)
{
    __shared__ float4 sc4[32], sh4[32];
    if (threadIdx.x < 128) {
        int j = threadIdx.x;
        float s = gamma[j] * rsqrtf(var[j] + 1e-5f);
        ((float*)sc4)[j] = s;
        ((float*)sh4)[j] = beta[j] - mean[j] * s;
    }
    __syncthreads();

    int idx = blockIdx.x * blockDim.x + threadIdx.x;
    int warp = idx >> 5;
    int lane = idx & 31;
    int row0 = warp << 1;
    int row1 = row0 + 1;
    if (row0 >= NN) return;
    bool has1 = (row1 < NN);

    int s0 = rowPtr[row0];
    int d0 = rowPtr[row0 + 1] - s0;
    int s1 = has1 ? rowPtr[row1] : 0;
    int d1 = has1 ? (rowPtr[row1 + 1] - s1) : 0;
    int dm = max(d0, d1);

    float4 a0 = make_float4(0.f, 0.f, 0.f, 0.f);
    float4 a1 = make_float4(0.f, 0.f, 0.f, 0.f);
    const uint2* hn2 = (const uint2*)hn;

#pragma unroll 2
    for (int j = 0; j < dm; j++) {
        int2 c0 = make_int2(0, 0), c1 = make_int2(0, 0);
        if (j < d0) c0 = __ldg(&csr[s0 + j]);
        if (j < d1) c1 = __ldg(&csr[s1 + j]);
        uint2 u0 = make_uint2(0u, 0u), u1 = make_uint2(0u, 0u);
        if (j < d0) u0 = hn2[(size_t)c0.x * 32 + lane];
        if (j < d1) u1 = hn2[(size_t)c1.x * 32 + lane];
        float w0 = __int_as_float(c0.y);   // 0.0f when OOB
        float w1 = __int_as_float(c1.y);
        float2 f0a = __half22float2(*reinterpret_cast<__half2*>(&u0.x));
        float2 f0b = __half22float2(*reinterpret_cast<__half2*>(&u0.y));
        float2 f1a = __half22float2(*reinterpret_cast<__half2*>(&u1.x));
        float2 f1b = __half22float2(*reinterpret_cast<__half2*>(&u1.y));
        a0.x += w0 * f0a.x; a0.y += w0 * f0a.y;
        a0.z += w0 * f0b.x; a0.w += w0 * f0b.y;
        a1.x += w1 * f1a.x; a1.y += w1 * f1a.y;
        a1.z += w1 * f1b.x; a1.w += w1 * f1b.y;
    }

    float4 scv = sc4[lane], shv = sh4[lane];

    // row0 epilogue
    {
        float4 hv = ((float4*)h)[(size_t)row0 * 32 + lane];
        hv.x += fmaxf(fmaf(a0.x, scv.x, shv.x), 0.f);
        hv.y += fmaxf(fmaf(a0.y, scv.y, shv.y), 0.f);
        hv.z += fmaxf(fmaf(a0.z, scv.z, shv.z), 0.f);
        hv.w += fmaxf(fmaf(a0.w, scv.w, shv.w), 0.f);
        ((float4*)h)[(size_t)row0 * 32 + lane] = hv;
        if (doGate) {
            float4 gw = ((const float4*)gateW)[lane];
            float d = hv.x * gw.x + hv.y * gw.y + hv.z * gw.z + hv.w * gw.w;
#pragma unroll
            for (int off = 16; off; off >>= 1) d += __shfl_xor_sync(0xFFFFFFFFu, d, off);
            if (lane == 0) gateOut[row0] = d + gateB[0];
        }
    }
    // row1 epilogue
    if (has1) {
        float4 hv = ((float4*)h)[(size_t)row1 * 32 + lane];
        hv.x += fmaxf(fmaf(a1.x, scv.x, shv.x), 0.f);
        hv.y += fmaxf(fmaf(a1.y, scv.y, shv.y), 0.f);
        hv.z += fmaxf(fmaf(a1.z, scv.z, shv.z), 0.f);
        hv.w += fmaxf(fmaf(a1.w, scv.w, shv.w), 0.f);
        ((float4*)h)[(size_t)row1 * 32 + lane] = hv;
        if (doGate) {
            float4 gw = ((const float4*)gateW)[lane];
            float d = hv.x * gw.x + hv.y * gw.y + hv.z * gw.z + hv.w * gw.w;
#pragma unroll
            for (int off = 16; off; off >>= 1) d += __shfl_xor_sync(0xFFFFFFFFu, d, off);
            if (lane == 0) gateOut[row1] = d + gateB[0];
        }
    }
}

// ---------------- per-graph softmax stats (max, 1/sumexp) ----------------
__global__ void seg_stats_kernel(const float* __restrict__ g,
                                 const int* __restrict__ batch,
                                 float* __restrict__ mOut,
                                 float* __restrict__ invOut)
{
    int b = blockIdx.x;
    int tid = threadIdx.x;  // 128

    int lo = 0, hi = NN;
    while (lo < hi) { int mid = (lo + hi) >> 1; if (batch[mid] < b) lo = mid + 1; else hi = mid; }
    int start = lo;
    hi = NN;
    while (lo < hi) { int mid = (lo + hi) >> 1; if (batch[mid] < b + 1) lo = mid + 1; else hi = mid; }
    int end = lo;

    __shared__ float red[128];
    float lm = -3.402823466e38f;
    for (int i = start + tid; i < end; i += 128) lm = fmaxf(lm, g[i]);
    red[tid] = lm; __syncthreads();
    for (int s = 64; s; s >>= 1) { if (tid < s) red[tid] = fmaxf(red[tid], red[tid + s]); __syncthreads(); }
    float m = red[0]; __syncthreads();

    float ls = 0.f;
    for (int i = start + tid; i < end; i += 128) ls += expf(g[i] - m);
    red[tid] = ls; __syncthreads();
    for (int s = 64; s; s >>= 1) { if (tid < s) red[tid] += red[tid + s]; __syncthreads(); }
    if (tid == 0) { mOut[b] = m; invOut[b] = 1.f / (red[0] + 1e-10f); }
}

// ---------------- weighted-sum pooling (bandwidth-parallel) ---------------
__global__ void pool_accum_kernel(const float* __restrict__ h,
                                  const float* __restrict__ g,
                                  const int* __restrict__ batch,
                                  const float* __restrict__ mIn,
                                  const float* __restrict__ invIn,
                                  float* __restrict__ emb)
{
    __shared__ float coef[256];
    __shared__ int sbat[256];
    int tid = threadIdx.x;      // 128
    int base = blockIdx.x * 256;
    if (base >= NN) return;

    for (int j = tid; j < 256; j += 128) {
        int i = base + j;
        if (i < NN) {
            int bb = batch[i];
            sbat[j] = bb;
            coef[j] = expf(g[i] - mIn[bb]) * invIn[bb];
        } else {
            sbat[j] = batch[NN - 1];
            coef[j] = 0.f;
        }
    }
    __syncthreads();

    float acc = 0.f;
    int cur = sbat[0];
    int cnt = min(256, NN - base);
#pragma unroll 4
    for (int j = 0; j < 256; j++) {
        if (j >= cnt) break;
        int bb = sbat[j];
        if (bb != cur) {
            atomicAdd(&emb[cur * 128 + tid], acc);
            acc = 0.f;
            cur = bb;
        }
        acc += coef[j] * h[(size_t)(base + j) * 128 + tid];
    }
    atomicAdd(&emb[cur * 128 + tid], acc);
}

// ---------------- head MLP ------------------------------------------------
__global__ void head_kernel(const float* __restrict__ emb,
                            const float* __restrict__ W1,
                            const float* __restrict__ b1,
                            const float* __restrict__ W2,
                            const float* __restrict__ b2,
                            float* __restrict__ out)
{
    int b = blockIdx.x;
    int tid = threadIdx.x;  // 128
    __shared__ float se[128], st[128];
    se[tid] = emb[b * 128 + tid];
    __syncthreads();
    float acc = b1[tid];
#pragma unroll 8
    for (int k = 0; k < 128; k++) acc += se[k] * W1[k * 128 + tid];
    st[tid] = fmaxf(acc, 0.f);
    __syncthreads();
    if (tid < OUTD) {
        float o = b2[tid];
#pragma unroll 8
        for (int k = 0; k < 128; k++) o += st[k] * W2[k * OUTD + tid];
        out[b * OUTD + tid] = o;
    }
}

// ---------------- launcher ----------------------------------------------
extern "C" void kernel_launch(void* const* d_in, const int* in_sizes, int n_in,
                              void* d_out, int out_size)
{
    const float* x        = (const float*)d_in[0];
    const float* edge_w   = (const float*)d_in[1];
    const float* W_in     = (const float*)d_in[2];
    const float* b_in     = (const float*)d_in[3];
    const float* conv_W   = (const float*)d_in[4];
    const float* conv_b   = (const float*)d_in[5];
    const float* bn_gamma = (const float*)d_in[6];
    const float* bn_beta  = (const float*)d_in[7];
    const float* bn_mean  = (const float*)d_in[8];
    const float* bn_var   = (const float*)d_in[9];
    const float* gate_W   = (const float*)d_in[10];
    const float* gate_b   = (const float*)d_in[11];
    const float* head_W1  = (const float*)d_in[12];
    const float* head_b1  = (const float*)d_in[13];
    const float* head_W2  = (const float*)d_in[14];
    const float* head_b2  = (const float*)d_in[15];
    const int*   er       = (const int*)d_in[16];
    const int*   ec       = (const int*)d_in[17];
    const int*   batch    = (const int*)d_in[18];
    float* out = (float*)d_out;

    float *h, *gate, *emb, *mArr, *invArr;
    __half *tmp, *wst;
    int *rowPtr, *cursor;
    int2 *csr;
    cudaGetSymbolAddress((void**)&h,      g_h);
    cudaGetSymbolAddress((void**)&tmp,    g_tmp);
    cudaGetSymbolAddress((void**)&gate,   g_gate);
    cudaGetSymbolAddress((void**)&emb,    g_emb);
    cudaGetSymbolAddress((void**)&mArr,   g_m);
    cudaGetSymbolAddress((void**)&invArr, g_invs);
    cudaGetSymbolAddress((void**)&rowPtr, g_rowPtr);
    cudaGetSymbolAddress((void**)&cursor, g_cursor);
    cudaGetSymbolAddress((void**)&csr,    g_csr);
    cudaGetSymbolAddress((void**)&wst,    g_wst);

    cudaFuncSetAttribute(gemm_f16_kernel,
                         cudaFuncAttributeMaxDynamicSharedMemorySize, GEMM_SMEM_H);

    const int gemmGrid = (NN + 63) / 64;            // 782
    const int edgeGrid = (EE + 255) / 256;          // 2344
    const int spmmGrid = ((NN + 1) / 2 * 32 + 255) / 256;   // 3125
    const int poolGrid = (NN + 255) / 256;          // 196

    // ---- fork: CSR build on side stream, overlapped with prep + GEMMs ----
    cudaStream_t s2;
    cudaEvent_t evFork, evJoin;
    cudaStreamCreateWithFlags(&s2, cudaStreamNonBlocking);
    cudaEventCreateWithFlags(&evFork, cudaEventDisableTiming);
    cudaEventCreateWithFlags(&evJoin, cudaEventDisableTiming);

    cudaEventRecord(evFork, 0);
    cudaStreamWaitEvent(s2, evFork, 0);

    // side stream: CSR build chain
    cudaMemsetAsync(cursor, 0, NN * sizeof(int), s2);
    deg_kernel<<<edgeGrid, 256, 0, s2>>>(er, cursor);
    scan_kernel<<<1, 1024, 0, s2>>>(cursor, rowPtr);
    fill_kernel<<<edgeGrid, 256, 0, s2>>>(er, ec, edge_w, cursor, csr);
    cudaEventRecord(evJoin, s2);

    // main stream: weight prep + input projection + first conv GEMM
    prep_w_kernel<<<128, 256>>>(W_in, conv_W, wst);
    gemm_f16_kernel<<<gemmGrid, 256, GEMM_SMEM_H>>>(x, wst, b_in, h, (__half*)0,
                                                    NN, 1, 0);
    gemm_f16_kernel<<<gemmGrid, 256, GEMM_SMEM_H>>>(
        h, wst + (size_t)1 * 16384, conv_b + 0 * HH, (float*)0, tmp, NN, 0, 1);

    // join: first spmm needs the CSR
    cudaStreamWaitEvent(0, evJoin, 0);

    for (int l = 0; l < LL; l++) {
        if (l > 0) {
            gemm_f16_kernel<<<gemmGrid, 256, GEMM_SMEM_H>>>(
                h, wst + (size_t)(l + 1) * 16384, conv_b + l * HH,
                (float*)0, tmp, NN, 0, 1);
        }
        spmm_fused_kernel<<<spmmGrid, 256>>>(tmp, rowPtr, csr, h,
                                             bn_gamma + l * HH, bn_beta + l * HH,
                                             bn_mean + l * HH, bn_var + l * HH,
                                             gate_W, gate_b, gate,
                                             (l == LL - 1) ? 1 : 0);
    }

    seg_stats_kernel<<<GG, 128>>>(gate, batch, mArr, invArr);
    cudaMemsetAsync(emb, 0, GG * HH * sizeof(float));
    pool_accum_kernel<<<poolGrid, 128>>>(h, gate, batch, mArr, invArr, emb);
    head_kernel<<<GG, 128>>>(emb, head_W1, head_b1, head_W2, head_b2, out);

    cudaEventDestroy(evFork);
    cudaEventDestroy(evJoin);
    cudaStreamDestroy(s2);
}

// round 12
// speedup vs baseline: 1.1686x; 1.1015x over previous
#include <cuda_runtime.h>
#include <cuda_fp16.h>
#include <math.h>
#include <stdint.h>

#define NN 50000
#define EE 600000
#define HH 128
#define GG 128
#define LL 3
#define OUTD 16

// ---------------- scratch (device globals; no allocation) ----------------
__device__ __align__(256) float  g_h[(size_t)NN * HH];    // node features fp32
__device__ __align__(256) __half g_tmp[(size_t)NN * HH];  // GEMM output fp16
__device__ __align__(256) float  g_gate[NN];              // gate logits
__device__ __align__(256) float  g_emb[GG * HH];          // graph embeddings
__device__ __align__(256) float  g_m[GG];                 // per-graph max
__device__ __align__(256) float  g_invs[GG];              // per-graph 1/sumexp
__device__ __align__(1024) __half g_wst[4 * 16384];       // transposed fp16 W
// CSR scratch: packed (col, weight-bits) per edge
__device__ __align__(256) int   g_rowPtr[NN + 1];
__device__ __align__(256) int   g_cursor[NN];
__device__ __align__(256) int2  g_csr[EE];

// ---------------- fp16 MMA helper ----------------
__device__ __forceinline__ void mma_f16(float* c, const uint32_t* a, const uint32_t* b) {
    asm volatile(
        "mma.sync.aligned.m16n8k16.row.col.f32.f16.f16.f32 "
        "{%0,%1,%2,%3},{%4,%5,%6,%7},{%8,%9},{%0,%1,%2,%3};"
        : "+f"(c[0]), "+f"(c[1]), "+f"(c[2]), "+f"(c[3])
        : "r"(a[0]), "r"(a[1]), "r"(a[2]), "r"(a[3]), "r"(b[0]), "r"(b[1]));
}

__device__ __forceinline__ uint32_t h2_u32(__half2 h) {
    return *reinterpret_cast<uint32_t*>(&h);
}

// ---------------- W prep: transpose + fp16 (coalesced reads) -------------
__global__ void prep_w_kernel(const float* __restrict__ W0,
                              const float* __restrict__ Wc,
                              __half* __restrict__ out)
{
    int i = blockIdx.x * blockDim.x + threadIdx.x;  // 0..32767
    if (i >= 32768) return;
    int wsel = i >> 13;
    int j = i & 8191;
    int n = j & 127;      // fastest -> coalesced read of W rows
    int k2 = j >> 7;      // k-pair 0..63
    const float* W = (wsel == 0) ? W0 : (Wc + (size_t)(wsel - 1) * 16384);
    __half2 p = __floats2half2_rn(W[(k2 * 2 + 0) * 128 + n],
                                  W[(k2 * 2 + 1) * 128 + n]);
    *(__half2*)(out + (size_t)wsel * 16384 + n * 128 + k2 * 2) = p;
}

// ---------------- fp16 tensor GEMM ----------------
// 64-row tile, 256 threads, 3 CTAs/SM. smem: Wt[128][136]h + A[64][136]h.
#define SPADH 136
#define SPADB (SPADH * 2)
#define GEMM_SMEM_H ((128 * SPADH + 64 * SPADH) * 2)

__global__ void __launch_bounds__(256, 3)
gemm_f16_kernel(const float* __restrict__ A,
                const __half* __restrict__ Wt,
                const float* __restrict__ bias,
                float* __restrict__ Cf,
                __half* __restrict__ Ch,
                int nrows, int doRelu, int outHalf)
{
    extern __shared__ __half smh[];
    char* Wsb = (char*)smh;                       // 128 x 272B
    char* Asb = (char*)(smh + 128 * SPADH);       // 64 x 272B

    int tid = threadIdx.x;
    int rowBase = blockIdx.x << 6;

    // stage W: straight copy of prepped [n][k] fp16 image
    const uint4* Wg = (const uint4*)Wt;
#pragma unroll
    for (int i = tid; i < 2048; i += 256) {
        int r = i >> 4, q = i & 15;
        *(uint4*)(Wsb + r * SPADB + q * 16) = Wg[i];
    }
    // stage A: fp32 -> fp16 convert
    const float4* Ag4 = (const float4*)A;
#pragma unroll
    for (int i = tid; i < 2048; i += 256) {
        int r = i >> 5, c4 = i & 31;
        int gr = rowBase + r;
        float4 v = (gr < nrows) ? Ag4[(size_t)gr * 32 + c4]
                                : make_float4(0.f, 0.f, 0.f, 0.f);
        __half2 p0 = __floats2half2_rn(v.x, v.y);
        __half2 p1 = __floats2half2_rn(v.z, v.w);
        *(uint2*)(Asb + r * SPADB + c4 * 8) = make_uint2(h2_u32(p0), h2_u32(p1));
    }
    __syncthreads();

    int wid = tid >> 5, lane = tid & 31;
    int wm = wid & 1;
    int wn = wid >> 1;
    int gq = lane >> 2;
    int tq = lane & 3;

    float acc[2][4][4];
#pragma unroll
    for (int mi = 0; mi < 2; mi++)
#pragma unroll
        for (int ni = 0; ni < 4; ni++)
#pragma unroll
            for (int j = 0; j < 4; j++) acc[mi][ni][j] = 0.f;

#pragma unroll
    for (int s = 0; s < 8; s++) {
        int kb = (s << 5) + tq * 4;
        uint32_t a[2][4];
#pragma unroll
        for (int mi = 0; mi < 2; mi++) {
            const char* base = Asb + ((wm << 5) + (mi << 4) + gq) * SPADB + kb;
            a[mi][0] = *(const uint32_t*)(base);
            a[mi][1] = *(const uint32_t*)(base + 8 * SPADB);
            a[mi][2] = *(const uint32_t*)(base + 16);
            a[mi][3] = *(const uint32_t*)(base + 8 * SPADB + 16);
        }
        uint32_t b[4][2];
#pragma unroll
        for (int ni = 0; ni < 4; ni++) {
            const char* base = Wsb + ((wn << 5) + (ni << 3) + gq) * SPADB + kb;
            b[ni][0] = *(const uint32_t*)(base);
            b[ni][1] = *(const uint32_t*)(base + 16);
        }
#pragma unroll
        for (int mi = 0; mi < 2; mi++)
#pragma unroll
            for (int ni = 0; ni < 4; ni++)
                mma_f16(acc[mi][ni], a[mi], b[ni]);
    }

#pragma unroll
    for (int mi = 0; mi < 2; mi++) {
        int r0 = rowBase + (wm << 5) + (mi << 4) + gq;
#pragma unroll
        for (int ni = 0; ni < 4; ni++) {
            int col = (wn << 5) + (ni << 3) + (tq << 1);
            float b0 = bias[col], b1 = bias[col + 1];
            float v0 = acc[mi][ni][0] + b0, v1 = acc[mi][ni][1] + b1;
            float v2 = acc[mi][ni][2] + b0, v3 = acc[mi][ni][3] + b1;
            if (doRelu) {
                v0 = fmaxf(v0, 0.f); v1 = fmaxf(v1, 0.f);
                v2 = fmaxf(v2, 0.f); v3 = fmaxf(v3, 0.f);
            }
            if (outHalf) {
                if (r0 < nrows)
                    *(uint32_t*)(Ch + (size_t)r0 * 128 + col) = h2_u32(__floats2half2_rn(v0, v1));
                if (r0 + 8 < nrows)
                    *(uint32_t*)(Ch + (size_t)(r0 + 8) * 128 + col) = h2_u32(__floats2half2_rn(v2, v3));
            } else {
                if (r0 < nrows)     *(float2*)(Cf + (size_t)r0 * 128 + col)       = make_float2(v0, v1);
                if (r0 + 8 < nrows) *(float2*)(Cf + (size_t)(r0 + 8) * 128 + col) = make_float2(v2, v3);
            }
        }
    }
}

// ---------------- CSR build (scalar, packed payload) ----------------------
__global__ void deg_kernel(const int* __restrict__ er, int* __restrict__ deg)
{
    int e = blockIdx.x * blockDim.x + threadIdx.x;
    if (e < EE) atomicAdd(&deg[er[e]], 1);
}

__global__ void scan_kernel(int* __restrict__ cursor, int* __restrict__ rowPtr)
{
    const int PER = (NN + 1023) / 1024;
    int tid = threadIdx.x;
    int base = tid * PER;

    int s = 0;
    for (int i = 0; i < PER; i++) {
        int idx = base + i;
        if (idx < NN) s += cursor[idx];
    }
    int lane = tid & 31, wid = tid >> 5;
    int ws = s;
#pragma unroll
    for (int off = 1; off < 32; off <<= 1) {
        int n = __shfl_up_sync(0xFFFFFFFFu, ws, off);
        if (lane >= off) ws += n;
    }
    __shared__ int wsum[32];
    if (lane == 31) wsum[wid] = ws;
    __syncthreads();
    if (wid == 0) {
        int v = wsum[lane];
#pragma unroll
        for (int off = 1; off < 32; off <<= 1) {
            int n = __shfl_up_sync(0xFFFFFFFFu, v, off);
            if (lane >= off) v += n;
        }
        wsum[lane] = v;
    }
    __syncthreads();
    int offset = ws - s + (wid ? wsum[wid - 1] : 0);

    int run = offset;
    for (int i = 0; i < PER; i++) {
        int idx = base + i;
        if (idx < NN) {
            int v = cursor[idx];
            rowPtr[idx] = run;
            cursor[idx] = run;
            run += v;
        }
    }
    if (tid == 1023) rowPtr[NN] = run;
}

__global__ void fill_kernel(const int* __restrict__ er, const int* __restrict__ ec,
                            const float* __restrict__ ew,
                            int* __restrict__ cursor,
                            int2* __restrict__ csr)
{
    int e = blockIdx.x * blockDim.x + threadIdx.x;
    if (e >= EE) return;
    int r = er[e];
    int c = ec[e];
    float w = ew[e];
    int pos = atomicAdd(&cursor[r], 1);
    csr[pos] = make_int2(c, __float_as_int(w));
}

// ------- fused SpMM-gather(fp16) + BN + ReLU + residual (+opt gate) -------
// one warp per row; lane owns features 4*lane..4*lane+3 (uint2 = 4 halves).
// (R8 configuration — best measured; R6/R10/R11 restructurings all regressed.)
__global__ void spmm_fused_kernel(const __half* __restrict__ hn,
                                  const int* __restrict__ rowPtr,
                                  const int2* __restrict__ csr,
                                  float* __restrict__ h,
                                  const float* __restrict__ gamma,
                                  const float* __restrict__ beta,
                                  const float* __restrict__ mean,
                                  const float* __restrict__ var,
                                  const float* __restrict__ gateW,
                                  const float* __restrict__ gateB,
                                  float* __restrict__ gateOut,
                                  int doGate)
{
    __shared__ float4 sc4[32], sh4[32];
    if (threadIdx.x < 128) {
        int j = threadIdx.x;
        float s = gamma[j] * rsqrtf(var[j] + 1e-5f);
        ((float*)sc4)[j] = s;
        ((float*)sh4)[j] = beta[j] - mean[j] * s;
    }
    __syncthreads();

    int idx = blockIdx.x * blockDim.x + threadIdx.x;
    int row = idx >> 5;
    int lane = idx & 31;
    if (row >= NN) return;

    int start = rowPtr[row];
    int end = rowPtr[row + 1];

    float4 s = make_float4(0.f, 0.f, 0.f, 0.f);
    const uint2* hn2 = (const uint2*)hn;
#pragma unroll 4
    for (int j = start; j < end; j++) {
        int2 e = __ldg(&csr[j]);        // uniform across warp: col + weight
        float w = __int_as_float(e.y);
        uint2 u = hn2[(size_t)e.x * 32 + lane];
        float2 fa = __half22float2(*reinterpret_cast<__half2*>(&u.x));
        float2 fb = __half22float2(*reinterpret_cast<__half2*>(&u.y));
        s.x += w * fa.x; s.y += w * fa.y;
        s.z += w * fb.x; s.w += w * fb.y;
    }

    float4 scv = sc4[lane], shv = sh4[lane];
    float4 hv = ((float4*)h)[(size_t)row * 32 + lane];
    hv.x += fmaxf(fmaf(s.x, scv.x, shv.x), 0.f);
    hv.y += fmaxf(fmaf(s.y, scv.y, shv.y), 0.f);
    hv.z += fmaxf(fmaf(s.z, scv.z, shv.z), 0.f);
    hv.w += fmaxf(fmaf(s.w, scv.w, shv.w), 0.f);
    ((float4*)h)[(size_t)row * 32 + lane] = hv;

    if (doGate) {
        float4 gw = ((const float4*)gateW)[lane];
        float d = hv.x * gw.x + hv.y * gw.y + hv.z * gw.z + hv.w * gw.w;
#pragma unroll
        for (int off = 16; off; off >>= 1) d += __shfl_xor_sync(0xFFFFFFFFu, d, off);
        if (lane == 0) gateOut[row] = d + gateB[0];
    }
}

// ------ per-graph softmax stats (max, 1/sumexp) + emb zeroing ------------
__global__ void seg_stats_kernel(const float* __restrict__ g,
                                 const int* __restrict__ batch,
                                 float* __restrict__ mOut,
                                 float* __restrict__ invOut,
                                 float* __restrict__ emb)
{
    int b = blockIdx.x;
    int tid = threadIdx.x;  // 128

    // zero this graph's embedding row (replaces separate memset; pool's
    // atomics are stream-ordered after this kernel)
    emb[b * 128 + tid] = 0.f;

    int lo = 0, hi = NN;
    while (lo < hi) { int mid = (lo + hi) >> 1; if (batch[mid] < b) lo = mid + 1; else hi = mid; }
    int start = lo;
    hi = NN;
    while (lo < hi) { int mid = (lo + hi) >> 1; if (batch[mid] < b + 1) lo = mid + 1; else hi = mid; }
    int end = lo;

    __shared__ float red[128];
    float lm = -3.402823466e38f;
    for (int i = start + tid; i < end; i += 128) lm = fmaxf(lm, g[i]);
    red[tid] = lm; __syncthreads();
    for (int s = 64; s; s >>= 1) { if (tid < s) red[tid] = fmaxf(red[tid], red[tid + s]); __syncthreads(); }
    float m = red[0]; __syncthreads();

    float ls = 0.f;
    for (int i = start + tid; i < end; i += 128) ls += expf(g[i] - m);
    red[tid] = ls; __syncthreads();
    for (int s = 64; s; s >>= 1) { if (tid < s) red[tid] += red[tid + s]; __syncthreads(); }
    if (tid == 0) { mOut[b] = m; invOut[b] = 1.f / (red[0] + 1e-10f); }
}

// ---------------- weighted-sum pooling (bandwidth-parallel) ---------------
__global__ void pool_accum_kernel(const float* __restrict__ h,
                                  const float* __restrict__ g,
                                  const int* __restrict__ batch,
                                  const float* __restrict__ mIn,
                                  const float* __restrict__ invIn,
                                  float* __restrict__ emb)
{
    __shared__ float coef[256];
    __shared__ int sbat[256];
    int tid = threadIdx.x;      // 128
    int base = blockIdx.x * 256;
    if (base >= NN) return;

    for (int j = tid; j < 256; j += 128) {
        int i = base + j;
        if (i < NN) {
            int bb = batch[i];
            sbat[j] = bb;
            coef[j] = expf(g[i] - mIn[bb]) * invIn[bb];
        } else {
            sbat[j] = batch[NN - 1];
            coef[j] = 0.f;
        }
    }
    __syncthreads();

    float acc = 0.f;
    int cur = sbat[0];
    int cnt = min(256, NN - base);
#pragma unroll 4
    for (int j = 0; j < 256; j++) {
        if (j >= cnt) break;
        int bb = sbat[j];
        if (bb != cur) {
            atomicAdd(&emb[cur * 128 + tid], acc);
            acc = 0.f;
            cur = bb;
        }
        acc += coef[j] * h[(size_t)(base + j) * 128 + tid];
    }
    atomicAdd(&emb[cur * 128 + tid], acc);
}

// ---------------- head MLP ------------------------------------------------
__global__ void head_kernel(const float* __restrict__ emb,
                            const float* __restrict__ W1,
                            const float* __restrict__ b1,
                            const float* __restrict__ W2,
                            const float* __restrict__ b2,
                            float* __restrict__ out)
{
    int b = blockIdx.x;
    int tid = threadIdx.x;  // 128
    __shared__ float se[128], st[128];
    se[tid] = emb[b * 128 + tid];
    __syncthreads();
    float acc = b1[tid];
#pragma unroll 8
    for (int k = 0; k < 128; k++) acc += se[k] * W1[k * 128 + tid];
    st[tid] = fmaxf(acc, 0.f);
    __syncthreads();
    if (tid < OUTD) {
        float o = b2[tid];
#pragma unroll 8
        for (int k = 0; k < 128; k++) o += st[k] * W2[k * OUTD + tid];
        out[b * OUTD + tid] = o;
    }
}

// ---------------- launcher ----------------------------------------------
extern "C" void kernel_launch(void* const* d_in, const int* in_sizes, int n_in,
                              void* d_out, int out_size)
{
    const float* x        = (const float*)d_in[0];
    const float* edge_w   = (const float*)d_in[1];
    const float* W_in     = (const float*)d_in[2];
    const float* b_in     = (const float*)d_in[3];
    const float* conv_W   = (const float*)d_in[4];
    const float* conv_b   = (const float*)d_in[5];
    const float* bn_gamma = (const float*)d_in[6];
    const float* bn_beta  = (const float*)d_in[7];
    const float* bn_mean  = (const float*)d_in[8];
    const float* bn_var   = (const float*)d_in[9];
    const float* gate_W   = (const float*)d_in[10];
    const float* gate_b   = (const float*)d_in[11];
    const float* head_W1  = (const float*)d_in[12];
    const float* head_b1  = (const float*)d_in[13];
    const float* head_W2  = (const float*)d_in[14];
    const float* head_b2  = (const float*)d_in[15];
    const int*   er       = (const int*)d_in[16];
    const int*   ec       = (const int*)d_in[17];
    const int*   batch    = (const int*)d_in[18];
    float* out = (float*)d_out;

    float *h, *gate, *emb, *mArr, *invArr;
    __half *tmp, *wst;
    int *rowPtr, *cursor;
    int2 *csr;
    cudaGetSymbolAddress((void**)&h,      g_h);
    cudaGetSymbolAddress((void**)&tmp,    g_tmp);
    cudaGetSymbolAddress((void**)&gate,   g_gate);
    cudaGetSymbolAddress((void**)&emb,    g_emb);
    cudaGetSymbolAddress((void**)&mArr,   g_m);
    cudaGetSymbolAddress((void**)&invArr, g_invs);
    cudaGetSymbolAddress((void**)&rowPtr, g_rowPtr);
    cudaGetSymbolAddress((void**)&cursor, g_cursor);
    cudaGetSymbolAddress((void**)&csr,    g_csr);
    cudaGetSymbolAddress((void**)&wst,    g_wst);

    cudaFuncSetAttribute(gemm_f16_kernel,
                         cudaFuncAttributeMaxDynamicSharedMemorySize, GEMM_SMEM_H);

    const int gemmGrid = (NN + 63) / 64;            // 782
    const int edgeGrid = (EE + 255) / 256;          // 2344
    const int spmmGrid = (NN * 32 + 255) / 256;     // 6250
    const int poolGrid = (NN + 255) / 256;          // 196

    // ---- fork: CSR build on side stream, overlapped with prep + GEMMs ----
    cudaStream_t s2;
    cudaEvent_t evFork, evJoin;
    cudaStreamCreateWithFlags(&s2, cudaStreamNonBlocking);
    cudaEventCreateWithFlags(&evFork, cudaEventDisableTiming);
    cudaEventCreateWithFlags(&evJoin, cudaEventDisableTiming);

    cudaEventRecord(evFork, 0);
    cudaStreamWaitEvent(s2, evFork, 0);

    // side stream: CSR build chain
    cudaMemsetAsync(cursor, 0, NN * sizeof(int), s2);
    deg_kernel<<<edgeGrid, 256, 0, s2>>>(er, cursor);
    scan_kernel<<<1, 1024, 0, s2>>>(cursor, rowPtr);
    fill_kernel<<<edgeGrid, 256, 0, s2>>>(er, ec, edge_w, cursor, csr);
    cudaEventRecord(evJoin, s2);

    // main stream: weight prep + input projection + first conv GEMM
    prep_w_kernel<<<128, 256>>>(W_in, conv_W, wst);
    gemm_f16_kernel<<<gemmGrid, 256, GEMM_SMEM_H>>>(x, wst, b_in, h, (__half*)0,
                                                    NN, 1, 0);
    gemm_f16_kernel<<<gemmGrid, 256, GEMM_SMEM_H>>>(
        h, wst + (size_t)1 * 16384, conv_b + 0 * HH, (float*)0, tmp, NN, 0, 1);

    // join: first spmm needs the CSR
    cudaStreamWaitEvent(0, evJoin, 0);

    for (int l = 0; l < LL; l++) {
        if (l > 0) {
            gemm_f16_kernel<<<gemmGrid, 256, GEMM_SMEM_H>>>(
                h, wst + (size_t)(l + 1) * 16384, conv_b + l * HH,
                (float*)0, tmp, NN, 0, 1);
        }
        spmm_fused_kernel<<<spmmGrid, 256>>>(tmp, rowPtr, csr, h,
                                             bn_gamma + l * HH, bn_beta + l * HH,
                                             bn_mean + l * HH, bn_var + l * HH,
                                             gate_W, gate_b, gate,
                                             (l == LL - 1) ? 1 : 0);
    }

    seg_stats_kernel<<<GG, 128>>>(gate, batch, mArr, invArr, emb);
    pool_accum_kernel<<<poolGrid, 128>>>(h, gate, batch, mArr, invArr, emb);
    head_kernel<<<GG, 128>>>(emb, head_W1, head_b1, head_W2, head_b2, out);

    cudaEventDestroy(evFork);
    cudaEventDestroy(evJoin);
    cudaStreamDestroy(s2);
}